// round 10
// baseline (speedup 1.0000x reference)
#include <cuda_runtime.h>
#include <cuda_fp16.h>
#include <cstdint>

#define NN 100000
#define EE_MAX 3200000
#define DD 128

typedef unsigned long long ull;

// Scratch (device globals; no allocation allowed)
__device__ __align__(16) __half g_Zh[NN * DD]; // transformed messages (fp16)
__device__ __align__(16) float g_R[NN * DD];   // root path (fp32)
__device__ __align__(16) float g_H[NN * DD];   // layer-1 output (fp32)
__device__ int g_CNT[NN];                      // in-degree
__device__ int g_ROWPTR[NN];                   // CSR row starts
__device__ int g_CUR[NN];                      // fill cursors
__device__ int g_EIDX[EE_MAX];                 // CSR column (src) indices
__device__ int g_BSUM[128];                    // scan block sums
__device__ int g_IS64;                         // edge_index dtype flag

#define SCAN_BLK 1024
#define NBLK_SCAN ((NN + SCAN_BLK - 1) / SCAN_BLK)

// ---------------------------------------------------------------------------
// f32x2 packed-FMA helpers (sm_103a FFMA2; exact fp32, 2 FMAs per issue)
// ---------------------------------------------------------------------------
__device__ __forceinline__ ull dup2(float x) {
    ull r;
    asm("mov.b64 %0, {%1, %1};" : "=l"(r) : "f"(x));
    return r;
}
__device__ __forceinline__ void fma2(ull& d, ull a, ull b) {
    asm("fma.rn.f32x2 %0, %1, %2, %0;" : "+l"(d) : "l"(a), "l"(b));
}
__device__ __forceinline__ void unpk(float& lo, float& hi, ull v) {
    asm("mov.b64 {%0, %1}, %2;" : "=f"(lo), "=f"(hi) : "l"(v));
}

// ---------------------------------------------------------------------------
// Edge-index dtype detection: int64 node ids are < NN; int32 pairs read as
// int64 have a random id in the high word -> value >= 2^32 almost surely.
// ---------------------------------------------------------------------------
__global__ void detect_kernel(const void* __restrict__ ei) {
    if (blockIdx.x == 0 && threadIdx.x == 0) {
        const long long* p = (const long long*)ei;
        int is64 = 1;
        for (int i = 0; i < 16; i++) {
            long long v = p[i];
            if (v < 0 || v >= (long long)NN) { is64 = 0; break; }
        }
        g_IS64 = is64;
    }
}

__device__ __forceinline__ int edge_at(const void* ei, int is64, int i) {
    if (is64) return (int)((const long long*)ei)[i];
    return ((const int*)ei)[i];
}

// ---------------------------------------------------------------------------
__global__ void zero_cnt_kernel() {
    int i = blockIdx.x * blockDim.x + threadIdx.x;
    if (i < NN) g_CNT[i] = 0;
}

// dst values live at element offsets [E, 2E)
__global__ void count_kernel(const void* __restrict__ ei, int E) {
    int i = blockIdx.x * blockDim.x + threadIdx.x;
    int stride = gridDim.x * blockDim.x;
    const int is64 = g_IS64;
    for (; i < E; i += stride) {
        int d = edge_at(ei, is64, E + i);
        if ((unsigned)d < (unsigned)NN) atomicAdd(&g_CNT[d], 1);
    }
}

// ---------------------------------------------------------------------------
// Exclusive scan of g_CNT -> g_ROWPTR, three phases.
// ---------------------------------------------------------------------------
__global__ __launch_bounds__(SCAN_BLK)
void scan1_kernel() {
    __shared__ int s[SCAN_BLK];
    int t = threadIdx.x;
    int gi = blockIdx.x * SCAN_BLK + t;
    int v = (gi < NN) ? g_CNT[gi] : 0;
    s[t] = v;
    __syncthreads();
    for (int off = 1; off < SCAN_BLK; off <<= 1) {
        int add = (t >= off) ? s[t - off] : 0;
        __syncthreads();
        s[t] += add;
        __syncthreads();
    }
    if (gi < NN) g_ROWPTR[gi] = s[t] - v;  // exclusive
    if (t == SCAN_BLK - 1) g_BSUM[blockIdx.x] = s[t];
}

__global__ void scan2_kernel() {
    if (threadIdx.x == 0) {
        int acc = 0;
        for (int b = 0; b < NBLK_SCAN; b++) {
            int v = g_BSUM[b];
            g_BSUM[b] = acc;
            acc += v;
        }
    }
}

__global__ void scan3_kernel() {
    int gi = blockIdx.x * blockDim.x + threadIdx.x;
    if (gi < NN) {
        int r = g_ROWPTR[gi] + g_BSUM[gi / SCAN_BLK];
        g_ROWPTR[gi] = r;
        g_CUR[gi] = r;
    }
}

// ---------------------------------------------------------------------------
// CSR fill: eidx[cursor[dst]++] = src
// ---------------------------------------------------------------------------
__global__ void fill_kernel(const void* __restrict__ ei, int E) {
    int i = blockIdx.x * blockDim.x + threadIdx.x;
    int stride = gridDim.x * blockDim.x;
    const int is64 = g_IS64;
    for (; i < E; i += stride) {
        int s = edge_at(ei, is64, i);
        int d = edge_at(ei, is64, E + i);
        if ((unsigned)d < (unsigned)NN && (unsigned)s < (unsigned)NN) {
            int pos = atomicAdd(&g_CUR[d], 1);
            if ((unsigned)pos < (unsigned)EE_MAX) g_EIDX[pos] = s;
        }
    }
}

// ---------------------------------------------------------------------------
// Dual GEMM via packed FFMA2 with PRE-DUPLICATED weights in smem.
// g_Zh(fp16) = A @ WL^T, g_R(fp32) = A @ WR^T.
// Lane l handles output cols {2l, 2l+1, 64+2l, 65+2l}; weight loads are
// 512B-contiguous per warp -> conflict-free LDS.128 of (w,w) pairs, so the
// inner loop has ZERO dup movs: 4 LDS.128 + 4 LDS.64 + 32 FFMA2 per k-step.
// Accumulators pack adjacent NODES: acc[pair][col] = (node 2p, node 2p+1).
// ---------------------------------------------------------------------------
#define KC 16
#define WPADP 260   // 256 packed floats + pad (multiple of 4; 1040B rows)
#define NPAD 66

template <bool UseH>
__global__ __launch_bounds__(256)
void gemm_dual(const float* __restrict__ Aext,
               const float* __restrict__ WL, const float* __restrict__ WR,
               int N) {
    __shared__ float sWL[KC * WPADP];  // [k][2*o .. 2*o+1] = W[o][kc+k] dup
    __shared__ float sWR[KC * WPADP];
    __shared__ float sA[KC * NPAD];    // [k][n]

    const float* A = UseH ? (const float*)g_H : Aext;

    const int t = threadIdx.x;
    const int n0 = blockIdx.x * 64;
    const int l = t & 31;          // lane -> cols {2l,2l+1,64+2l,65+2l}
    const int gg = t >> 5;         // node group: 8 nodes (4 pairs)

    ull accL[4][4], accR[4][4];    // [node pair][col slot]
#pragma unroll
    for (int p = 0; p < 4; p++)
#pragma unroll
        for (int j = 0; j < 4; j++) { accL[p][j] = 0ULL; accR[p][j] = 0ULL; }

    for (int kc = 0; kc < 128; kc += KC) {
        if (kc) __syncthreads();
        // Weights duplicated: sW[k*WPADP + 2o] = sW[.. + 2o+1] = W[o*128+kc+k]
        for (int idx = t; idx < KC * 128; idx += 256) {
            int k = idx & (KC - 1);
            int o = idx >> 4;
            float wl = WL[o * 128 + kc + k];
            float wr = WR[o * 128 + kc + k];
            *(ull*)&sWL[k * WPADP + 2 * o] = dup2(wl);
            *(ull*)&sWR[k * WPADP + 2 * o] = dup2(wr);
        }
        // A transposed into [k][n]
        for (int idx = t; idx < 64 * KC; idx += 256) {
            int k = idx & (KC - 1);
            int n = idx >> 4;
            int row = n0 + n;
            sA[k * NPAD + n] = (row < N) ? A[(size_t)row * 128 + kc + k] : 0.0f;
        }
        __syncthreads();

#pragma unroll
        for (int k = 0; k < KC; k++) {
            // cols {2l,2l+1} dup'd: words [4l..4l+3]; cols {64+2l,65+2l}: +128
            const ull* w1L = (const ull*)&sWL[k * WPADP + 4 * l];
            const ull* w2L = (const ull*)&sWL[k * WPADP + 128 + 4 * l];
            const ull* w1R = (const ull*)&sWR[k * WPADP + 4 * l];
            const ull* w2R = (const ull*)&sWR[k * WPADP + 128 + 4 * l];
            ull wl0 = w1L[0], wl1 = w1L[1], wl2 = w2L[0], wl3 = w2L[1];
            ull wr0 = w1R[0], wr1 = w1R[1], wr2 = w2R[0], wr3 = w2R[1];
            const ull* ap = (const ull*)&sA[k * NPAD + gg * 8];  // broadcast
#pragma unroll
            for (int p = 0; p < 4; p++) {
                ull a2 = ap[p];   // (a[2p], a[2p+1])
                fma2(accL[p][0], a2, wl0);
                fma2(accL[p][1], a2, wl1);
                fma2(accL[p][2], a2, wl2);
                fma2(accL[p][3], a2, wl3);
                fma2(accR[p][0], a2, wr0);
                fma2(accR[p][1], a2, wr1);
                fma2(accR[p][2], a2, wr2);
                fma2(accR[p][3], a2, wr3);
            }
        }
    }

    // Epilogue: lane l writes cols {2l,2l+1} and {64+2l,65+2l}.
#pragma unroll
    for (int p = 0; p < 4; p++) {
        int r0 = n0 + gg * 8 + 2 * p;
        int r1 = r0 + 1;
        float zl0[4], zl1[4], zr0[4], zr1[4];
#pragma unroll
        for (int j = 0; j < 4; j++) {
            unpk(zl0[j], zl1[j], accL[p][j]);
            unpk(zr0[j], zr1[j], accR[p][j]);
        }
        if (r0 < N) {
            __half2* z = (__half2*)(g_Zh + (size_t)r0 * 128);
            z[l]      = __floats2half2_rn(zl0[0], zl0[1]);
            z[32 + l] = __floats2half2_rn(zl0[2], zl0[3]);
            float2* r = (float2*)(g_R + (size_t)r0 * 128);
            r[l]      = make_float2(zr0[0], zr0[1]);
            r[32 + l] = make_float2(zr0[2], zr0[3]);
        }
        if (r1 < N) {
            __half2* z = (__half2*)(g_Zh + (size_t)r1 * 128);
            z[l]      = __floats2half2_rn(zl1[0], zl1[1]);
            z[32 + l] = __floats2half2_rn(zl1[2], zl1[3]);
            float2* r = (float2*)(g_R + (size_t)r1 * 128);
            r[l]      = make_float2(zr1[0], zr1[1]);
            r[32 + l] = make_float2(zr1[2], zr1[3]);
        }
    }
}

// ---------------------------------------------------------------------------
// Fused aggregate + node update. One warp per node; Z rows are fp16 (8B/lane).
// h = relu(mean_{s in row} Z[s] + bl + R[n])
// MODE 0: write H row (fp32).  MODE 1: out[n] = h . Wc + bc (classifier).
// ---------------------------------------------------------------------------
template <int MODE>
__global__ __launch_bounds__(256)
void sage_agg(const float* __restrict__ bl,
              const float* __restrict__ Wc,
              const float* __restrict__ bc,
              float* __restrict__ out, int N) {
    int warp = (blockIdx.x * blockDim.x + threadIdx.x) >> 5;
    int lane = threadIdx.x & 31;
    if (warp >= N) return;

    const int base = g_ROWPTR[warp];
    const int len = g_CNT[warp];
    const int o4 = lane * 4;

    float4 acc = make_float4(0.f, 0.f, 0.f, 0.f);
    for (int j0 = 0; j0 < len; j0 += 32) {
        int rem = len - j0;
        int m = (rem < 32) ? rem : 32;
        int myidx = (lane < m) ? g_EIDX[base + j0 + lane] : 0;
        for (int t = 0; t < m; t++) {
            int s = __shfl_sync(0xFFFFFFFFu, myidx, t);
            ull raw = *(const ull*)(g_Zh + (size_t)s * 128 + o4);
            __half2 h01 = ((const __half2*)&raw)[0];
            __half2 h23 = ((const __half2*)&raw)[1];
            float2 f01 = __half22float2(h01);
            float2 f23 = __half22float2(h23);
            acc.x += f01.x; acc.y += f01.y; acc.z += f23.x; acc.w += f23.y;
        }
    }

    float inv = 1.0f / fmaxf((float)len, 1.0f);
    float4 r = *(const float4*)(g_R + (size_t)warp * 128 + o4);
    float4 b = *(const float4*)&bl[o4];
    float4 h;
    h.x = fmaxf(fmaf(acc.x, inv, b.x + r.x), 0.0f);
    h.y = fmaxf(fmaf(acc.y, inv, b.y + r.y), 0.0f);
    h.z = fmaxf(fmaf(acc.z, inv, b.z + r.z), 0.0f);
    h.w = fmaxf(fmaf(acc.w, inv, b.w + r.w), 0.0f);

    if (MODE == 0) {
        *(float4*)(g_H + (size_t)warp * 128 + o4) = h;
    } else {
        float4 wc = *(const float4*)&Wc[o4];
        float s = h.x * wc.x + h.y * wc.y + h.z * wc.z + h.w * wc.w;
#pragma unroll
        for (int off = 16; off; off >>= 1)
            s += __shfl_down_sync(0xFFFFFFFFu, s, off);
        if (lane == 0) out[warp] = s + bc[0];
    }
}

// ---------------------------------------------------------------------------
extern "C" void kernel_launch(void* const* d_in, const int* in_sizes, int n_in,
                              void* d_out, int out_size) {
    const float* x   = (const float*)d_in[0];
    const void* ei   = d_in[1];
    const float* Wl1 = (const float*)d_in[2];
    const float* bl1 = (const float*)d_in[3];
    const float* Wr1 = (const float*)d_in[4];
    const float* Wl2 = (const float*)d_in[5];
    const float* bl2 = (const float*)d_in[6];
    const float* Wr2 = (const float*)d_in[7];
    const float* Wc  = (const float*)d_in[8];
    const float* bc  = (const float*)d_in[9];
    float* out       = (float*)d_out;

    const int N = in_sizes[0] / DD;
    const int E = in_sizes[1] / 2;

    const int gemm_blocks = (N + 63) / 64;
    const int agg_blocks = (N + 7) / 8;   // 8 warps per block

    // ---- CSR build ----
    detect_kernel<<<1, 32>>>(ei);
    zero_cnt_kernel<<<(NN + 255) / 256, 256>>>();
    count_kernel<<<2048, 256>>>(ei, E);
    scan1_kernel<<<NBLK_SCAN, SCAN_BLK>>>();
    scan2_kernel<<<1, 32>>>();
    scan3_kernel<<<(NN + 255) / 256, 256>>>();
    fill_kernel<<<2048, 256>>>(ei, E);

    // ---- Layer 1 ----
    gemm_dual<false><<<gemm_blocks, 256>>>(x, Wl1, Wr1, N);
    sage_agg<0><<<agg_blocks, 256>>>(bl1, nullptr, nullptr, nullptr, N);

    // ---- Layer 2 + classifier ----
    gemm_dual<true><<<gemm_blocks, 256>>>(nullptr, Wl2, Wr2, N);
    sage_agg<1><<<agg_blocks, 256>>>(bl2, Wc, bc, out, N);
}

// round 17
// speedup vs baseline: 1.2816x; 1.2816x over previous
#include <cuda_runtime.h>
#include <cuda_fp16.h>
#include <cstdint>

#define NN 100000
#define EE_MAX 3200000
#define DD 128

typedef unsigned long long ull;

// Scratch (device globals; no allocation allowed)
__device__ __align__(16) __half g_Zh[NN * DD]; // transformed messages (fp16)
__device__ __align__(16) float g_R[NN * DD];   // root path (fp32)
__device__ __align__(16) float g_H[NN * DD];   // layer-1 output (fp32)
__device__ int g_CNT[NN];                      // in-degree
__device__ int g_ROWPTR[NN];                   // CSR row starts
__device__ int g_CUR[NN];                      // fill cursors
__device__ int g_EIDX[EE_MAX];                 // CSR column (src) indices
__device__ int g_BSUM[128];                    // scan block sums
__device__ int g_IS64;                         // edge_index dtype flag

#define SCAN_BLK 1024
#define NBLK_SCAN ((NN + SCAN_BLK - 1) / SCAN_BLK)

// ---------------------------------------------------------------------------
// f32x2 packed-FMA helpers (sm_103a FFMA2; exact fp32, 2 FMAs per issue)
// ---------------------------------------------------------------------------
__device__ __forceinline__ ull dup2(float x) {
    ull r;
    asm("mov.b64 %0, {%1, %1};" : "=l"(r) : "f"(x));
    return r;
}
__device__ __forceinline__ void fma2(ull& d, ull a, ull b) {
    asm("fma.rn.f32x2 %0, %1, %2, %0;" : "+l"(d) : "l"(a), "l"(b));
}
__device__ __forceinline__ void unpk(float& lo, float& hi, ull v) {
    asm("mov.b64 {%0, %1}, %2;" : "=f"(lo), "=f"(hi) : "l"(v));
}
__device__ __forceinline__ unsigned pack_h2(float a, float b) {
    __half2 h = __floats2half2_rn(a, b);
    return *(unsigned*)&h;
}

// ---------------------------------------------------------------------------
// Edge-index dtype detection: int64 node ids are < NN; int32 pairs read as
// int64 have a random id in the high word -> value >= 2^32 almost surely.
// ---------------------------------------------------------------------------
__global__ void detect_kernel(const void* __restrict__ ei) {
    if (blockIdx.x == 0 && threadIdx.x == 0) {
        const long long* p = (const long long*)ei;
        int is64 = 1;
        for (int i = 0; i < 16; i++) {
            long long v = p[i];
            if (v < 0 || v >= (long long)NN) { is64 = 0; break; }
        }
        g_IS64 = is64;
    }
}

__device__ __forceinline__ int edge_at(const void* ei, int is64, int i) {
    if (is64) return (int)((const long long*)ei)[i];
    return ((const int*)ei)[i];
}

// ---------------------------------------------------------------------------
__global__ void zero_cnt_kernel() {
    int i = blockIdx.x * blockDim.x + threadIdx.x;
    if (i < NN) g_CNT[i] = 0;
}

// dst values live at element offsets [E, 2E)
__global__ void count_kernel(const void* __restrict__ ei, int E) {
    int i = blockIdx.x * blockDim.x + threadIdx.x;
    int stride = gridDim.x * blockDim.x;
    const int is64 = g_IS64;
    for (; i < E; i += stride) {
        int d = edge_at(ei, is64, E + i);
        if ((unsigned)d < (unsigned)NN) atomicAdd(&g_CNT[d], 1);
    }
}

// ---------------------------------------------------------------------------
// Exclusive scan of g_CNT -> g_ROWPTR, three phases.
// ---------------------------------------------------------------------------
__global__ __launch_bounds__(SCAN_BLK)
void scan1_kernel() {
    __shared__ int s[SCAN_BLK];
    int t = threadIdx.x;
    int gi = blockIdx.x * SCAN_BLK + t;
    int v = (gi < NN) ? g_CNT[gi] : 0;
    s[t] = v;
    __syncthreads();
    for (int off = 1; off < SCAN_BLK; off <<= 1) {
        int add = (t >= off) ? s[t - off] : 0;
        __syncthreads();
        s[t] += add;
        __syncthreads();
    }
    if (gi < NN) g_ROWPTR[gi] = s[t] - v;  // exclusive
    if (t == SCAN_BLK - 1) g_BSUM[blockIdx.x] = s[t];
}

__global__ void scan2_kernel() {
    if (threadIdx.x == 0) {
        int acc = 0;
        for (int b = 0; b < NBLK_SCAN; b++) {
            int v = g_BSUM[b];
            g_BSUM[b] = acc;
            acc += v;
        }
    }
}

__global__ void scan3_kernel() {
    int gi = blockIdx.x * blockDim.x + threadIdx.x;
    if (gi < NN) {
        int r = g_ROWPTR[gi] + g_BSUM[gi / SCAN_BLK];
        g_ROWPTR[gi] = r;
        g_CUR[gi] = r;
    }
}

// ---------------------------------------------------------------------------
// CSR fill: eidx[cursor[dst]++] = src
// ---------------------------------------------------------------------------
__global__ void fill_kernel(const void* __restrict__ ei, int E) {
    int i = blockIdx.x * blockDim.x + threadIdx.x;
    int stride = gridDim.x * blockDim.x;
    const int is64 = g_IS64;
    for (; i < E; i += stride) {
        int s = edge_at(ei, is64, i);
        int d = edge_at(ei, is64, E + i);
        if ((unsigned)d < (unsigned)NN && (unsigned)s < (unsigned)NN) {
            int pos = atomicAdd(&g_CUR[d], 1);
            if ((unsigned)pos < (unsigned)EE_MAX) g_EIDX[pos] = s;
        }
    }
}

// ---------------------------------------------------------------------------
// Dual GEMM via packed FFMA2 (R8 structure — known good).
// g_Zh(fp16) = A @ WL^T, g_R(fp32) = A @ WR^T.
// Accumulators pack adjacent NODES: acc[pair][out] = (node 2p, node 2p+1).
// sA stored transposed [k][n] (NPAD even -> aligned LDS.64; warp-uniform
// address -> smem broadcast). Weight scalars dup-packed (w,w) per k (MOVs
// ride the ALU pipe under the FFMA2 shadow).
// WPAD multiple of 4 (float4 LDS.128 alignment).
// ---------------------------------------------------------------------------
#define KC 32
#define WPAD 132
#define NPAD 66

template <bool UseH>
__global__ __launch_bounds__(256)
void gemm_dual(const float* __restrict__ Aext,
               const float* __restrict__ WL, const float* __restrict__ WR,
               int N) {
    __shared__ float sWL[KC * WPAD];
    __shared__ float sWR[KC * WPAD];
    __shared__ float sA[KC * NPAD];   // [k][n]

    const float* A = UseH ? (const float*)g_H : Aext;

    const int t = threadIdx.x;
    const int n0 = blockIdx.x * 64;
    const int o4 = (t & 31) * 4;   // 4 consecutive output cols
    const int gg = t >> 5;         // node group: 8 nodes (4 pairs)

    ull accL[4][4], accR[4][4];    // [node pair][output col]
#pragma unroll
    for (int p = 0; p < 4; p++)
#pragma unroll
        for (int j = 0; j < 4; j++) { accL[p][j] = 0ULL; accR[p][j] = 0ULL; }

    for (int kc = 0; kc < 128; kc += KC) {
        if (kc) __syncthreads();
        // Weights transposed: sW[k*WPAD + o] = W[o*128 + kc + k]
        for (int idx = t; idx < KC * 128; idx += 256) {
            int k = idx & 31;
            int o = idx >> 5;
            sWL[k * WPAD + o] = WL[o * 128 + kc + k];
            sWR[k * WPAD + o] = WR[o * 128 + kc + k];
        }
        // A transposed into [k][n]: sA[k*NPAD + n] = A[(n0+n)*128 + kc + k]
        for (int idx = t; idx < 64 * KC; idx += 256) {
            int k = idx & 31;   // lane -> coalesced global read
            int n = idx >> 5;
            int row = n0 + n;
            sA[k * NPAD + n] = (row < N) ? A[(size_t)row * 128 + kc + k] : 0.0f;
        }
        __syncthreads();

#pragma unroll 2
        for (int k = 0; k < KC; k++) {
            float4 wl = *(const float4*)&sWL[k * WPAD + o4];
            float4 wr = *(const float4*)&sWR[k * WPAD + o4];
            ull wlp[4] = { dup2(wl.x), dup2(wl.y), dup2(wl.z), dup2(wl.w) };
            ull wrp[4] = { dup2(wr.x), dup2(wr.y), dup2(wr.z), dup2(wr.w) };
            const ull* ap = (const ull*)&sA[k * NPAD + gg * 8];  // broadcast
#pragma unroll
            for (int p = 0; p < 4; p++) {
                ull a2 = ap[p];   // (a[2p], a[2p+1])
                fma2(accL[p][0], a2, wlp[0]);
                fma2(accL[p][1], a2, wlp[1]);
                fma2(accL[p][2], a2, wlp[2]);
                fma2(accL[p][3], a2, wlp[3]);
                fma2(accR[p][0], a2, wrp[0]);
                fma2(accR[p][1], a2, wrp[1]);
                fma2(accR[p][2], a2, wrp[2]);
                fma2(accR[p][3], a2, wrp[3]);
            }
        }
    }

#pragma unroll
    for (int p = 0; p < 4; p++) {
        int r0 = n0 + gg * 8 + 2 * p;
        int r1 = r0 + 1;
        float zl0[4], zl1[4], zr0[4], zr1[4];
#pragma unroll
        for (int j = 0; j < 4; j++) {
            unpk(zl0[j], zl1[j], accL[p][j]);
            unpk(zr0[j], zr1[j], accR[p][j]);
        }
        if (r0 < N) {
            *(uint2*)(g_Zh + (size_t)r0 * 128 + o4) =
                make_uint2(pack_h2(zl0[0], zl0[1]), pack_h2(zl0[2], zl0[3]));
            *(float4*)&g_R[(size_t)r0 * 128 + o4] =
                make_float4(zr0[0], zr0[1], zr0[2], zr0[3]);
        }
        if (r1 < N) {
            *(uint2*)(g_Zh + (size_t)r1 * 128 + o4) =
                make_uint2(pack_h2(zl1[0], zl1[1]), pack_h2(zl1[2], zl1[3]));
            *(float4*)&g_R[(size_t)r1 * 128 + o4] =
                make_float4(zr1[0], zr1[1], zr1[2], zr1[3]);
        }
    }
}

// ---------------------------------------------------------------------------
// Fused aggregate + node update. TWO nodes per warp (one per half-warp):
// fp16 Z rows are 256B, so 16 lanes cover a row with LDG.128 (8 halves/lane).
// Inner loop batches TWO neighbor-row loads back-to-back (MLP>=2 per
// half-warp) before converting/accumulating.
// h = relu(mean_{s in row} Z[s] + bl + R[n])
// MODE 0: write H row (fp32).  MODE 1: out[n] = h . Wc + bc (classifier).
// ---------------------------------------------------------------------------
__device__ __forceinline__ void acc_row(float* acc, const uint4& raw) {
    const __half2* hp = (const __half2*)&raw;
#pragma unroll
    for (int q = 0; q < 4; q++) {
        float2 f = __half22float2(hp[q]);
        acc[2 * q] += f.x;
        acc[2 * q + 1] += f.y;
    }
}

template <int MODE>
__global__ __launch_bounds__(256)
void sage_agg(const float* __restrict__ bl,
              const float* __restrict__ Wc,
              const float* __restrict__ bc,
              float* __restrict__ out, int N) {
    int warp = (blockIdx.x * blockDim.x + threadIdx.x) >> 5;
    int lane = threadIdx.x & 31;
    int hl = lane & 15;                   // lane within half-warp
    int node = warp * 2 + (lane >> 4);    // one node per half-warp
    if (node >= N) return;                // N even -> whole warp exits together

    const unsigned hmask = 0xFFFFu << (lane & 16);  // my half-warp's mask
    const int base = g_ROWPTR[node];
    const int len = g_CNT[node];
    const int h8 = hl * 8;                // 8 half-columns per lane

    float acc[8];
#pragma unroll
    for (int j = 0; j < 8; j++) acc[j] = 0.0f;

    for (int j0 = 0; j0 < len; j0 += 16) {
        int rem = len - j0;
        int m = (rem < 16) ? rem : 16;
        int myidx = (hl < m) ? g_EIDX[base + j0 + hl] : 0;
        int t = 0;
        for (; t + 2 <= m; t += 2) {
            int s0 = __shfl_sync(hmask, myidx, t, 16);
            int s1 = __shfl_sync(hmask, myidx, t + 1, 16);
            // issue both loads before any conversion -> MLP >= 2
            uint4 raw0 = *(const uint4*)(g_Zh + (size_t)s0 * 128 + h8);
            uint4 raw1 = *(const uint4*)(g_Zh + (size_t)s1 * 128 + h8);
            acc_row(acc, raw0);
            acc_row(acc, raw1);
        }
        if (t < m) {
            int s0 = __shfl_sync(hmask, myidx, t, 16);
            uint4 raw0 = *(const uint4*)(g_Zh + (size_t)s0 * 128 + h8);
            acc_row(acc, raw0);
        }
    }

    float inv = 1.0f / fmaxf((float)len, 1.0f);
    float4 r0 = *(const float4*)(g_R + (size_t)node * 128 + h8);
    float4 r1 = *(const float4*)(g_R + (size_t)node * 128 + h8 + 4);
    float4 b0 = *(const float4*)&bl[h8];
    float4 b1 = *(const float4*)&bl[h8 + 4];
    float h[8];
    h[0] = fmaxf(fmaf(acc[0], inv, b0.x + r0.x), 0.0f);
    h[1] = fmaxf(fmaf(acc[1], inv, b0.y + r0.y), 0.0f);
    h[2] = fmaxf(fmaf(acc[2], inv, b0.z + r0.z), 0.0f);
    h[3] = fmaxf(fmaf(acc[3], inv, b0.w + r0.w), 0.0f);
    h[4] = fmaxf(fmaf(acc[4], inv, b1.x + r1.x), 0.0f);
    h[5] = fmaxf(fmaf(acc[5], inv, b1.y + r1.y), 0.0f);
    h[6] = fmaxf(fmaf(acc[6], inv, b1.z + r1.z), 0.0f);
    h[7] = fmaxf(fmaf(acc[7], inv, b1.w + r1.w), 0.0f);

    if (MODE == 0) {
        *(float4*)(g_H + (size_t)node * 128 + h8) =
            make_float4(h[0], h[1], h[2], h[3]);
        *(float4*)(g_H + (size_t)node * 128 + h8 + 4) =
            make_float4(h[4], h[5], h[6], h[7]);
    } else {
        float4 w0 = *(const float4*)&Wc[h8];
        float4 w1 = *(const float4*)&Wc[h8 + 4];
        float s = h[0] * w0.x + h[1] * w0.y + h[2] * w0.z + h[3] * w0.w
                + h[4] * w1.x + h[5] * w1.y + h[6] * w1.z + h[7] * w1.w;
#pragma unroll
        for (int off = 8; off; off >>= 1)
            s += __shfl_down_sync(hmask, s, off, 16);
        if (hl == 0) out[node] = s + bc[0];
    }
}

// ---------------------------------------------------------------------------
extern "C" void kernel_launch(void* const* d_in, const int* in_sizes, int n_in,
                              void* d_out, int out_size) {
    const float* x   = (const float*)d_in[0];
    const void* ei   = d_in[1];
    const float* Wl1 = (const float*)d_in[2];
    const float* bl1 = (const float*)d_in[3];
    const float* Wr1 = (const float*)d_in[4];
    const float* Wl2 = (const float*)d_in[5];
    const float* bl2 = (const float*)d_in[6];
    const float* Wr2 = (const float*)d_in[7];
    const float* Wc  = (const float*)d_in[8];
    const float* bc  = (const float*)d_in[9];
    float* out       = (float*)d_out;

    const int N = in_sizes[0] / DD;
    const int E = in_sizes[1] / 2;

    const int gemm_blocks = (N + 63) / 64;
    const int agg_warps = (N + 1) / 2;
    const int agg_blocks = (agg_warps + 7) / 8;   // 8 warps per block

    // ---- CSR build ----
    detect_kernel<<<1, 32>>>(ei);
    zero_cnt_kernel<<<(NN + 255) / 256, 256>>>();
    count_kernel<<<2048, 256>>>(ei, E);
    scan1_kernel<<<NBLK_SCAN, SCAN_BLK>>>();
    scan2_kernel<<<1, 32>>>();
    scan3_kernel<<<(NN + 255) / 256, 256>>>();
    fill_kernel<<<2048, 256>>>(ei, E);

    // ---- Layer 1 ----
    gemm_dual<false><<<gemm_blocks, 256>>>(x, Wl1, Wr1, N);
    sage_agg<0><<<agg_blocks, 256>>>(bl1, nullptr, nullptr, nullptr, N);

    // ---- Layer 2 + classifier ----
    gemm_dual<true><<<gemm_blocks, 256>>>(nullptr, Wl2, Wr2, N);
    sage_agg<1><<<agg_blocks, 256>>>(bl2, Wc, bc, out, N);
}